// round 1
// baseline (speedup 1.0000x reference)
#include <cuda_runtime.h>

// knnLoss: B=4, downsample (400,400) stride 4 -> 100x100 = 10000 pts, 3-D.
// loss = mean_b [ mean_{n,d} (nearest_s - t)^2 ] = sum_{b,t} min_s ||s-t||^2 / 120000.
// Expanded form: ||s-t||^2 = ||t||^2 + (||s||^2 - 2 t.s); min over the parenthesized
// term (3 FFMA/pair), ||t||^2 added at reduction.

#define OUT_HW   100
#define STRIDE   4
#define NPTS     10000
#define NB       4
#define HW       400
#define PLANE    (HW * HW)        // 160000
#define SSPLIT   4
#define SCHUNK   (NPTS / SSPLIT)  // 2500
#define TCHUNK   256
#define NTCHUNK  ((NPTS + TCHUNK - 1) / TCHUNK)  // 40

__device__ float4 g_t[NB * NPTS];
__device__ float4 g_s[NB * NPTS];
__device__ float  g_partial[SSPLIT][NB * NPTS];

// ---------------------------------------------------------------------------
// Kernel 1: downsample + pack (x, y, z, |p|^2) per point into float4 arrays.
// ---------------------------------------------------------------------------
__global__ void pack_kernel(const float* __restrict__ tgt,
                            const float* __restrict__ src) {
    int i = blockIdx.x * blockDim.x + threadIdx.x;
    int total = 2 * NB * NPTS;
    if (i >= total) return;
    int which = i / (NB * NPTS);        // 0 = target, 1 = source
    int r = i - which * (NB * NPTS);
    int b = r / NPTS;
    int m = r - b * NPTS;
    int h = (m / OUT_HW) * STRIDE;
    int w = (m - (m / OUT_HW) * OUT_HW) * STRIDE;
    const float* p = (which == 0 ? tgt : src) + (size_t)b * 3 * PLANE + h * HW + w;
    float x = p[0];
    float y = p[PLANE];
    float z = p[2 * PLANE];
    float4 v = make_float4(x, y, z, fmaf(x, x, fmaf(y, y, z * z)));
    if (which == 0) g_t[r] = v; else g_s[r] = v;
}

// ---------------------------------------------------------------------------
// Kernel 2: for each (batch, t-chunk, s-chunk): min over 2500 source points of
// (|s|^2 - 2 t.s). One thread per t point; s chunk staged in smem (40KB).
// Grid (40, 4, 4) = 640 blocks x 256 threads.
// ---------------------------------------------------------------------------
__global__ void __launch_bounds__(TCHUNK)
min_kernel() {
    __shared__ float4 stile[SCHUNK];   // 40 KB

    int b  = blockIdx.y;
    int sc = blockIdx.z;

    // Cooperative load of this s-chunk (coalesced float4 from L2).
    const float4* sp = g_s + b * NPTS + sc * SCHUNK;
    #pragma unroll
    for (int j = threadIdx.x; j < SCHUNK; j += TCHUNK)
        stile[j] = sp[j];
    __syncthreads();

    int t  = blockIdx.x * TCHUNK + threadIdx.x;
    int tc = t < NPTS ? t : (NPTS - 1);        // clamp for tail block
    float4 tv = g_t[b * NPTS + tc];
    float m2x = -2.0f * tv.x;
    float m2y = -2.0f * tv.y;
    float m2z = -2.0f * tv.z;

    // 4 independent min accumulators (break FMNMX dependency chain).
    float m0 = 3.4e38f, m1 = 3.4e38f, m2 = 3.4e38f, m3 = 3.4e38f;

    #pragma unroll 2
    for (int j = 0; j < SCHUNK; j += 4) {
        float4 s0 = stile[j + 0];
        float4 s1 = stile[j + 1];
        float4 s2 = stile[j + 2];
        float4 s3 = stile[j + 3];
        float d0 = fmaf(s0.z, m2z, fmaf(s0.y, m2y, fmaf(s0.x, m2x, s0.w)));
        float d1 = fmaf(s1.z, m2z, fmaf(s1.y, m2y, fmaf(s1.x, m2x, s1.w)));
        float d2 = fmaf(s2.z, m2z, fmaf(s2.y, m2y, fmaf(s2.x, m2x, s2.w)));
        float d3 = fmaf(s3.z, m2z, fmaf(s3.y, m2y, fmaf(s3.x, m2x, s3.w)));
        m0 = fminf(m0, d0);
        m1 = fminf(m1, d1);
        m2 = fminf(m2, d2);
        m3 = fminf(m3, d3);
    }
    float m = fminf(fminf(m0, m1), fminf(m2, m3));

    if (t < NPTS)
        g_partial[sc][b * NPTS + t] = m;
}

// ---------------------------------------------------------------------------
// Kernel 3: combine s-split partials, add |t|^2, deterministic block reduce.
// ---------------------------------------------------------------------------
__global__ void reduce_kernel(float* __restrict__ out) {
    __shared__ float red[1024];
    float sum = 0.0f;
    for (int i = threadIdx.x; i < NB * NPTS; i += 1024) {
        float m = g_partial[0][i];
        m = fminf(m, g_partial[1][i]);
        m = fminf(m, g_partial[2][i]);
        m = fminf(m, g_partial[3][i]);
        sum += m + g_t[i].w;
    }
    red[threadIdx.x] = sum;
    __syncthreads();
    #pragma unroll
    for (int s = 512; s > 0; s >>= 1) {
        if (threadIdx.x < s) red[threadIdx.x] += red[threadIdx.x + s];
        __syncthreads();
    }
    if (threadIdx.x == 0)
        out[0] = red[0] * (1.0f / (float)(NB * NPTS * 3));
}

// ---------------------------------------------------------------------------
extern "C" void kernel_launch(void* const* d_in, const int* in_sizes, int n_in,
                              void* d_out, int out_size) {
    const float* tgt = (const float*)d_in[0];   // target_pc (4,3,400,400)
    const float* src = (const float*)d_in[1];   // source_pc (4,3,400,400)
    float* out = (float*)d_out;

    int pack_total = 2 * NB * NPTS;
    pack_kernel<<<(pack_total + 255) / 256, 256>>>(tgt, src);

    dim3 grid(NTCHUNK, NB, SSPLIT);
    min_kernel<<<grid, TCHUNK>>>();

    reduce_kernel<<<1, 1024>>>(out);
}

// round 3
// speedup vs baseline: 1.4828x; 1.4828x over previous
#include <cuda_runtime.h>
#include <cstdint>

// knnLoss: B=4, 400x400 stride-4 downsample -> 10000 pts x 3.
// loss = sum_{b,t} min_s ||s-t||^2 / 120000
//      = sum_{b,t} [ ||t||^2 + min_s (||s||^2 - 2 t.s) ] / 120000.
// Inner min uses packed fma.rn.f32x2 (2 source pts / instr), SoA smem tiles,
// 2 target pts per thread (each smem load reused twice).

#define OUT_HW   100
#define STRIDE   4
#define NPTS     10000
#define NB       4
#define HW       400
#define PLANE    (HW * HW)        // 160000
#define SSPLIT   10
#define SCHUNK   (NPTS / SSPLIT)  // 1000
#define NTHREADS 128
#define TPB      (NTHREADS * 2)   // 256 targets per block
#define NTCHUNK  ((NPTS + TPB - 1) / TPB)  // 40

__device__ float4 g_t[NB * NPTS];
__device__ float  g_sx[NB * NPTS];
__device__ float  g_sy[NB * NPTS];
__device__ float  g_sz[NB * NPTS];
__device__ float  g_sw[NB * NPTS];
__device__ float  g_partial[SSPLIT][NB * NPTS];

// ---- f32x2 helpers --------------------------------------------------------
__device__ __forceinline__ unsigned long long fma2(unsigned long long a,
                                                   unsigned long long b,
                                                   unsigned long long c) {
    unsigned long long d;
    asm("fma.rn.f32x2 %0, %1, %2, %3;" : "=l"(d) : "l"(a), "l"(b), "l"(c));
    return d;
}
__device__ __forceinline__ unsigned long long dup2(float v) {
    unsigned long long r;
    asm("mov.b64 %0, {%1, %1};" : "=l"(r) : "f"(v));
    return r;
}
__device__ __forceinline__ void unpack2(unsigned long long v, float& lo, float& hi) {
    asm("mov.b64 {%0, %1}, %2;" : "=f"(lo), "=f"(hi) : "l"(v));
}
// Load 4 consecutive floats from shared as two packed f32x2 (16B aligned).
__device__ __forceinline__ void lds_x4(const float* p,
                                       unsigned long long& a,
                                       unsigned long long& b) {
    uint32_t addr = (uint32_t)__cvta_generic_to_shared(p);
    asm volatile("ld.shared.v2.b64 {%0, %1}, [%2];"
                 : "=l"(a), "=l"(b) : "r"(addr));
}

// ---------------------------------------------------------------------------
// Kernel 1: downsample + pack. Target -> AoS float4 (x,y,z,|t|^2).
// Source -> SoA (x, y, z, |s|^2) for packed smem loads.
// ---------------------------------------------------------------------------
__global__ void pack_kernel(const float* __restrict__ tgt,
                            const float* __restrict__ src) {
    int i = blockIdx.x * blockDim.x + threadIdx.x;
    int total = 2 * NB * NPTS;
    if (i >= total) return;
    int which = i / (NB * NPTS);        // 0 = target, 1 = source
    int r = i - which * (NB * NPTS);
    int b = r / NPTS;
    int m = r - b * NPTS;
    int h = (m / OUT_HW) * STRIDE;
    int w = (m - (m / OUT_HW) * OUT_HW) * STRIDE;
    const float* p = (which == 0 ? tgt : src) + (size_t)b * 3 * PLANE + h * HW + w;
    float x = p[0];
    float y = p[PLANE];
    float z = p[2 * PLANE];
    float nrm = fmaf(x, x, fmaf(y, y, z * z));
    if (which == 0) {
        g_t[r] = make_float4(x, y, z, nrm);
    } else {
        g_sx[r] = x; g_sy[r] = y; g_sz[r] = z; g_sw[r] = nrm;
    }
}

// ---------------------------------------------------------------------------
// Kernel 2: per (t-chunk, batch, s-chunk) partial min of (|s|^2 - 2 t.s).
// Grid (40, 4, 10) = 1600 blocks x 128 threads; 2 targets/thread.
// ---------------------------------------------------------------------------
__global__ void __launch_bounds__(NTHREADS)
min_kernel() {
    __shared__ alignas(16) float sx[SCHUNK];
    __shared__ alignas(16) float sy[SCHUNK];
    __shared__ alignas(16) float sz[SCHUNK];
    __shared__ alignas(16) float sw[SCHUNK];

    int b  = blockIdx.y;
    int sc = blockIdx.z;
    int sbase = b * NPTS + sc * SCHUNK;

    for (int j = threadIdx.x; j < SCHUNK; j += NTHREADS) {
        sx[j] = g_sx[sbase + j];
        sy[j] = g_sy[sbase + j];
        sz[j] = g_sz[sbase + j];
        sw[j] = g_sw[sbase + j];
    }
    __syncthreads();

    int t0 = blockIdx.x * TPB + threadIdx.x;
    int t1 = t0 + NTHREADS;
    int t0c = t0 < NPTS ? t0 : (NPTS - 1);
    int t1c = t1 < NPTS ? t1 : (NPTS - 1);
    float4 tv0 = g_t[b * NPTS + t0c];
    float4 tv1 = g_t[b * NPTS + t1c];

    unsigned long long ax0 = dup2(-2.0f * tv0.x);
    unsigned long long ay0 = dup2(-2.0f * tv0.y);
    unsigned long long az0 = dup2(-2.0f * tv0.z);
    unsigned long long ax1 = dup2(-2.0f * tv1.x);
    unsigned long long ay1 = dup2(-2.0f * tv1.y);
    unsigned long long az1 = dup2(-2.0f * tv1.z);

    const float INF = 3.4e38f;
    float p0 = INF, p1 = INF, p2 = INF, p3 = INF;   // target t0 accumulators
    float q0 = INF, q1 = INF, q2 = INF, q3 = INF;   // target t1 accumulators

    #pragma unroll 2
    for (int j = 0; j < SCHUNK; j += 4) {
        unsigned long long x01, x23, y01, y23, z01, z23, w01, w23;
        lds_x4(&sx[j], x01, x23);
        lds_x4(&sy[j], y01, y23);
        lds_x4(&sz[j], z01, z23);
        lds_x4(&sw[j], w01, w23);

        unsigned long long d;
        float lo, hi;

        d = fma2(z01, az0, fma2(y01, ay0, fma2(x01, ax0, w01)));
        unpack2(d, lo, hi); p0 = fminf(p0, lo); p1 = fminf(p1, hi);
        d = fma2(z23, az0, fma2(y23, ay0, fma2(x23, ax0, w23)));
        unpack2(d, lo, hi); p2 = fminf(p2, lo); p3 = fminf(p3, hi);

        d = fma2(z01, az1, fma2(y01, ay1, fma2(x01, ax1, w01)));
        unpack2(d, lo, hi); q0 = fminf(q0, lo); q1 = fminf(q1, hi);
        d = fma2(z23, az1, fma2(y23, ay1, fma2(x23, ax1, w23)));
        unpack2(d, lo, hi); q2 = fminf(q2, lo); q3 = fminf(q3, hi);
    }

    float mp = fminf(fminf(p0, p1), fminf(p2, p3));
    float mq = fminf(fminf(q0, q1), fminf(q2, q3));

    if (t0 < NPTS) g_partial[sc][b * NPTS + t0] = mp;
    if (t1 < NPTS) g_partial[sc][b * NPTS + t1] = mq;
}

// ---------------------------------------------------------------------------
// Kernel 3: combine s-split partials, add |t|^2, deterministic reduce.
// ---------------------------------------------------------------------------
__global__ void reduce_kernel(float* __restrict__ out) {
    __shared__ float red[1024];
    float sum = 0.0f;
    for (int i = threadIdx.x; i < NB * NPTS; i += 1024) {
        float m = g_partial[0][i];
        #pragma unroll
        for (int s = 1; s < SSPLIT; s++)
            m = fminf(m, g_partial[s][i]);
        sum += m + g_t[i].w;
    }
    red[threadIdx.x] = sum;
    __syncthreads();
    #pragma unroll
    for (int s = 512; s > 0; s >>= 1) {
        if (threadIdx.x < s) red[threadIdx.x] += red[threadIdx.x + s];
        __syncthreads();
    }
    if (threadIdx.x == 0)
        out[0] = red[0] * (1.0f / (float)(NB * NPTS * 3));
}

// ---------------------------------------------------------------------------
extern "C" void kernel_launch(void* const* d_in, const int* in_sizes, int n_in,
                              void* d_out, int out_size) {
    const float* tgt = (const float*)d_in[0];   // target_pc (4,3,400,400)
    const float* src = (const float*)d_in[1];   // source_pc (4,3,400,400)
    float* out = (float*)d_out;

    int pack_total = 2 * NB * NPTS;
    pack_kernel<<<(pack_total + 255) / 256, 256>>>(tgt, src);

    dim3 grid(NTCHUNK, NB, SSPLIT);
    min_kernel<<<grid, NTHREADS>>>();

    reduce_kernel<<<1, 1024>>>(out);
}